// round 2
// baseline (speedup 1.0000x reference)
#include <cuda_runtime.h>
#include <math.h>

// Problem constants
#define BATCH 4
#define CH    256
#define REPC  128
#define HH    32
#define WWI   128
#define HW    4096              // H*W
#define NSIDE 2
#define BCHW  (BATCH*CH*HW)     // 4194304
#define BHW   (BATCH*HW)        // 16384

// -------- scratch (static device arrays; no runtime allocation) ----------
__device__ float g_theta[NSIDE*BATCH*HW*REPC];   // [s][b][p][r]
__device__ float g_phi  [NSIDE*BATCH*REPC*HW];   // [s][b][r][p]
__device__ float g_gv   [NSIDE*BATCH*HW*REPC];   // [s][b][p][r]
__device__ float g_after[NSIDE*BATCH*HW*REPC];   // [s][b][p][r]
__device__ float g_y    [NSIDE*BATCH*CH*HW];     // [s][b][c][p]
__device__ float g_stats[NSIDE*CH*2];            // [s][c][{sum,sumsq}]

__device__ __forceinline__ void cp_async16(void* smem_dst, const void* gsrc) {
    unsigned s = (unsigned)__cvta_generic_to_shared(smem_dst);
    asm volatile("cp.async.cg.shared.global [%0], [%1], 16;\n" :: "r"(s), "l"(gsrc));
}
#define CP_COMMIT() asm volatile("cp.async.commit_group;\n" ::: "memory")
#define CP_WAIT0()  asm volatile("cp.async.wait_group 0;\n" ::: "memory")

// =========================================================================
// Kernel A: projection GEMMs.  grid (32, B, 6): z = side*3 + type
//   type 0: theta -> g_theta (transposed [p][r]), + pre channel + query add
//   type 1: phi   -> g_phi   (natural [r][p]),    + key add
//   type 2: g     -> g_gv    (transposed [p][r])
// Block computes [128 r x 128 p], K=256 in chunks of 16, 256 thr, 8x8 micro.
// =========================================================================
__global__ __launch_bounds__(256) void proj_kernel(
    const float* __restrict__ left, const float* __restrict__ right,
    const float* __restrict__ pre_l, const float* __restrict__ pre_r,
    const float* __restrict__ query_l, const float* __restrict__ key_l,
    const float* __restrict__ query_r, const float* __restrict__ key_r,
    const float* __restrict__ theta_w, const float* __restrict__ theta_b,
    const float* __restrict__ phi_w, const float* __restrict__ phi_b,
    const float* __restrict__ gw, const float* __restrict__ gb)
{
    __shared__ float As[16][128];
    __shared__ float Bs[16][128];

    const int n0   = blockIdx.x * 128;
    const int b    = blockIdx.y;
    const int z    = blockIdx.z;
    const int side = z / 3;
    const int type = z - side * 3;

    const float* xq  = side ? right : left;
    const float* xkv = side ? left  : right;
    const float* X   = (type == 0) ? xq : xkv;
    const float* Wm  = (type == 0) ? theta_w : (type == 1 ? phi_w : gw);
    const float* bias= (type == 0) ? theta_b : (type == 1 ? phi_b : gb);
    const int    ldw = (type == 0) ? (CH + 1) : CH;
    X += (size_t)b * CH * HW;

    const int t  = threadIdx.x;
    const int tx = t & 15, ty = t >> 4;

    float acc[8][8];
    #pragma unroll
    for (int i = 0; i < 8; i++)
        #pragma unroll
        for (int j = 0; j < 8; j++) acc[i][j] = 0.f;

    for (int k0 = 0; k0 < CH; k0 += 16) {
        // --- load W chunk: As[kk][r] = Wm[r*ldw + k0+kk]
        if (type == 0) {
            // ldw = 257 (odd): scalar loads to keep alignment
            int r = t >> 1, kk8 = (t & 1) * 8;
            #pragma unroll
            for (int u = 0; u < 8; u++)
                As[kk8 + u][r] = Wm[(size_t)r * ldw + k0 + kk8 + u];
        } else {
            int r = t >> 2, kk4 = (t & 3) * 4;
            #pragma unroll
            for (int rr = 0; rr < 128; rr += 64) {
                float4 v = *(const float4*)&Wm[(size_t)(r + rr) * CH + k0 + kk4];
                As[kk4 + 0][r + rr] = v.x; As[kk4 + 1][r + rr] = v.y;
                As[kk4 + 2][r + rr] = v.z; As[kk4 + 3][r + rr] = v.w;
            }
        }
        // --- load X chunk: Bs[kk][p] = X[(k0+kk)*HW + n0 + p]
        {
            int kk = t >> 5, p4 = (t & 31) * 4;
            #pragma unroll
            for (int kr = 0; kr < 16; kr += 8)
                *(float4*)&Bs[kk + kr][p4] =
                    *(const float4*)&X[(size_t)(k0 + kk + kr) * HW + n0 + p4];
        }
        __syncthreads();
        #pragma unroll
        for (int kk = 0; kk < 16; kk++) {
            float4 a0 = *(const float4*)&As[kk][ty * 8];
            float4 a1 = *(const float4*)&As[kk][ty * 8 + 4];
            float4 b0 = *(const float4*)&Bs[kk][tx * 8];
            float4 b1 = *(const float4*)&Bs[kk][tx * 8 + 4];
            float a[8] = {a0.x, a0.y, a0.z, a0.w, a1.x, a1.y, a1.z, a1.w};
            float v[8] = {b0.x, b0.y, b0.z, b0.w, b1.x, b1.y, b1.z, b1.w};
            #pragma unroll
            for (int i = 0; i < 8; i++)
                #pragma unroll
                for (int j = 0; j < 8; j++)
                    acc[i][j] = fmaf(a[i], v[j], acc[i][j]);
        }
        __syncthreads();
    }

    const int sb = side * BATCH + b;
    if (type == 0) {
        const float* pre = side ? pre_r : pre_l;
        const float* qry = side ? query_r : query_l;
        float wp[8], pd[8];
        #pragma unroll
        for (int i = 0; i < 8; i++) wp[i] = Wm[(size_t)(ty * 8 + i) * ldw + CH];
        #pragma unroll
        for (int j = 0; j < 8; j++)
            pd[j] = pre[(size_t)b * HW + n0 + tx * 8 + j] * (1.0f / WWI);
        #pragma unroll
        for (int i = 0; i < 8; i++) {
            int r = ty * 8 + i;
            float bi = bias[r];
            #pragma unroll
            for (int j = 0; j < 8; j++) {
                int p = n0 + tx * 8 + j;
                acc[i][j] += wp[i] * pd[j] + bi +
                             qry[((size_t)b * REPC + r) * HW + p];
            }
        }
        #pragma unroll
        for (int j = 0; j < 8; j++) {
            int p = n0 + tx * 8 + j;
            float* o = &g_theta[((size_t)sb * HW + p) * REPC + ty * 8];
            *(float4*)&o[0] = make_float4(acc[0][j], acc[1][j], acc[2][j], acc[3][j]);
            *(float4*)&o[4] = make_float4(acc[4][j], acc[5][j], acc[6][j], acc[7][j]);
        }
    } else if (type == 1) {
        const float* keyf = side ? key_l : key_r;  // kv side is the opposite side
        #pragma unroll
        for (int i = 0; i < 8; i++) {
            int r = ty * 8 + i;
            float bi = bias[r];
            #pragma unroll
            for (int j = 0; j < 8; j++)
                acc[i][j] += bi + keyf[((size_t)b * REPC + r) * HW + n0 + tx * 8 + j];
            float* o = &g_phi[((size_t)sb * REPC + r) * HW + n0 + tx * 8];
            *(float4*)&o[0] = make_float4(acc[i][0], acc[i][1], acc[i][2], acc[i][3]);
            *(float4*)&o[4] = make_float4(acc[i][4], acc[i][5], acc[i][6], acc[i][7]);
        }
    } else {
        #pragma unroll
        for (int i = 0; i < 8; i++) {
            float bi = bias[ty * 8 + i];
            #pragma unroll
            for (int j = 0; j < 8; j++) acc[i][j] += bi;
        }
        #pragma unroll
        for (int j = 0; j < 8; j++) {
            int p = n0 + tx * 8 + j;
            float* o = &g_gv[((size_t)sb * HW + p) * REPC + ty * 8];
            *(float4*)&o[0] = make_float4(acc[0][j], acc[1][j], acc[2][j], acc[3][j]);
            *(float4*)&o[4] = make_float4(acc[4][j], acc[5][j], acc[6][j], acc[7][j]);
        }
    }
}

// =========================================================================
// Kernel B: fused flash-attention + soft-argmax, double-buffered K/V.
// grid (HW/64, B, 2); 256 threads. Q tile 64 x 128, K tile 64.
// Per thread: 4x4 S micro (ty,tx in 16x16) and 4x8 O micro.
// Dyn smem: Qs 32KB + 2*(Ks 16KB + Vs 32KB) + Ps 16KB = 144KB -> 1 CTA/SM.
// =========================================================================
#define KSZ (128*64)
#define VSZ (64*128)
#define ATTN_SMEM ((128*64 + 2*KSZ + 2*VSZ + 64*64) * 4)

__global__ __launch_bounds__(256) void attn_kernel(float* __restrict__ d_out)
{
    extern __shared__ float sm[];
    float* Qs  = sm;                    // [128][64] : Qs[d*64+q]
    float* Ksb = sm + 128 * 64;         // 2 x [128][64]
    float* Vsb = Ksb + 2 * KSZ;         // 2 x [64][128]
    float* Ps  = Vsb + 2 * VSZ;         // [64][64]

    const int q0   = blockIdx.x * 64;
    const int b    = blockIdx.y;
    const int side = blockIdx.z;
    const int sb   = side * BATCH + b;
    const int t    = threadIdx.x;
    const int tx   = t & 15, ty = t >> 4;

    const float* phi = &g_phi[(size_t)sb * REPC * HW];
    const float* gv  = &g_gv [(size_t)sb * HW * REPC];

    // per-thread fixed load mapping for K and V tiles
    const int kd  = t >> 4;          // 0..15 : K row-within-16
    const int kk4 = (t & 15) * 4;    // 0..60 : K col*4
    const int vk  = t >> 5;          // 0..7  : V row-within-8
    const int vr4 = (t & 31) * 4;    // 0..124: V col*4

    // prefetch tile 0 into buffer 0
    {
        #pragma unroll
        for (int dd = 0; dd < 8; dd++)
            cp_async16(&Ksb[(dd * 16 + kd) * 64 + kk4],
                       &phi[(size_t)(dd * 16 + kd) * HW + kk4]);
        #pragma unroll
        for (int kk = 0; kk < 8; kk++)
            cp_async16(&Vsb[(kk * 8 + vk) * 128 + vr4],
                       &gv[(size_t)(kk * 8 + vk) * REPC + vr4]);
        CP_COMMIT();
    }

    // load Q tile (transpose [p][r] -> Qs[d][q]) while K/V tile 0 in flight
    {
        const float* th = &g_theta[((size_t)sb * HW + q0) * REPC];
        int q = t >> 2, d4 = (t & 3) * 4;
        #pragma unroll
        for (int dd = 0; dd < 8; dd++) {
            float4 v = *(const float4*)&th[(size_t)q * REPC + dd * 16 + d4];
            int d = dd * 16 + d4;
            Qs[(d + 0) * 64 + q] = v.x; Qs[(d + 1) * 64 + q] = v.y;
            Qs[(d + 2) * 64 + q] = v.z; Qs[(d + 3) * 64 + q] = v.w;
        }
    }

    float O[4][8];
    float m[4], l[4], cacc[4];
    #pragma unroll
    for (int i = 0; i < 4; i++) {
        m[i] = -1e30f; l[i] = 0.f; cacc[i] = 0.f;
        #pragma unroll
        for (int j = 0; j < 8; j++) O[i][j] = 0.f;
    }

    CP_WAIT0();
    __syncthreads();

    for (int kt = 0; kt < 64; kt++) {
        const int cur = kt & 1;
        const float* Ks = Ksb + cur * KSZ;
        const float* Vs = Vsb + cur * VSZ;

        // issue async loads for next tile into the other buffer
        if (kt < 63) {
            const int k0n = (kt + 1) * 64;
            float* Kn = Ksb + (1 - cur) * KSZ;
            float* Vn = Vsb + (1 - cur) * VSZ;
            #pragma unroll
            for (int dd = 0; dd < 8; dd++)
                cp_async16(&Kn[(dd * 16 + kd) * 64 + kk4],
                           &phi[(size_t)(dd * 16 + kd) * HW + k0n + kk4]);
            #pragma unroll
            for (int kk = 0; kk < 8; kk++)
                cp_async16(&Vn[(kk * 8 + vk) * 128 + vr4],
                           &gv[(size_t)(k0n + kk * 8 + vk) * REPC + vr4]);
            CP_COMMIT();
        }

        // ---- S = Q^T K  (4x4 micro) ----
        const int k0 = kt * 64;
        float s_[4][4];
        #pragma unroll
        for (int i = 0; i < 4; i++)
            #pragma unroll
            for (int j = 0; j < 4; j++) s_[i][j] = 0.f;
        #pragma unroll 8
        for (int d = 0; d < 128; d++) {
            float4 aq = *(const float4*)&Qs[d * 64 + ty * 4];
            float4 bk = *(const float4*)&Ks[d * 64 + tx * 4];
            float av[4] = {aq.x, aq.y, aq.z, aq.w};
            float bv[4] = {bk.x, bk.y, bk.z, bk.w};
            #pragma unroll
            for (int i = 0; i < 4; i++)
                #pragma unroll
                for (int j = 0; j < 4; j++)
                    s_[i][j] = fmaf(av[i], bv[j], s_[i][j]);
        }

        // ---- online softmax per row (16-lane groups own a row) ----
        float osc[4];
        #pragma unroll
        for (int i = 0; i < 4; i++) {
            float mloc = fmaxf(fmaxf(s_[i][0], s_[i][1]), fmaxf(s_[i][2], s_[i][3]));
            #pragma unroll
            for (int off = 8; off >= 1; off >>= 1)
                mloc = fmaxf(mloc, __shfl_xor_sync(0xffffffffu, mloc, off));
            float mnew = fmaxf(m[i], mloc);
            float corr = __expf(m[i] - mnew);
            float ps = 0.f, cs = 0.f;
            #pragma unroll
            for (int j = 0; j < 4; j++) {
                float p = __expf(s_[i][j] - mnew);
                s_[i][j] = p;
                ps += p;
                cs += p * (float)((k0 + tx * 4 + j) & (WWI - 1));
            }
            #pragma unroll
            for (int off = 8; off >= 1; off >>= 1) {
                ps += __shfl_xor_sync(0xffffffffu, ps, off);
                cs += __shfl_xor_sync(0xffffffffu, cs, off);
            }
            l[i]    = l[i] * corr + ps;
            cacc[i] = cacc[i] * corr + cs;
            m[i]    = mnew;
            osc[i]  = corr;
            #pragma unroll
            for (int j = 0; j < 4; j++)
                Ps[(ty * 4 + i) * 64 + tx * 4 + j] = s_[i][j];
        }
        __syncthreads();

        // ---- O = O*corr + P V  (4x8 micro) ----
        #pragma unroll
        for (int i = 0; i < 4; i++)
            #pragma unroll
            for (int j = 0; j < 8; j++) O[i][j] *= osc[i];
        #pragma unroll 8
        for (int k = 0; k < 64; k++) {
            float a_[4];
            #pragma unroll
            for (int i = 0; i < 4; i++) a_[i] = Ps[(ty * 4 + i) * 64 + k];
            float4 v0 = *(const float4*)&Vs[k * 128 + tx * 8];
            float4 v1 = *(const float4*)&Vs[k * 128 + tx * 8 + 4];
            float bv[8] = {v0.x, v0.y, v0.z, v0.w, v1.x, v1.y, v1.z, v1.w};
            #pragma unroll
            for (int i = 0; i < 4; i++)
                #pragma unroll
                for (int j = 0; j < 8; j++)
                    O[i][j] = fmaf(a_[i], bv[j], O[i][j]);
        }
        CP_WAIT0();
        __syncthreads();
    }

    // ---- finalize: after = O/l ; index = q%W - exp_col ----
    #pragma unroll
    for (int i = 0; i < 4; i++) {
        int q = q0 + ty * 4 + i;
        float inv = 1.0f / l[i];
        float* o = &g_after[((size_t)sb * HW + q) * REPC + tx * 8];
        *(float4*)&o[0] = make_float4(O[i][0]*inv, O[i][1]*inv, O[i][2]*inv, O[i][3]*inv);
        *(float4*)&o[4] = make_float4(O[i][4]*inv, O[i][5]*inv, O[i][6]*inv, O[i][7]*inv);
        if (tx == 0)
            d_out[2 * (size_t)BCHW + (size_t)side * BHW + (size_t)b * HW + q] =
                (float)(q & (WWI - 1)) - cacc[i] * inv;
    }
}

// =========================================================================
// Kernel C: up-projection y = up_w @ after^T + up_b.
// grid (32, 2, 8): x = p tile, y = c tile, z = sb. Same 8x8 micro.
// =========================================================================
__global__ __launch_bounds__(256) void up_kernel(
    const float* __restrict__ up_w, const float* __restrict__ up_b)
{
    __shared__ float As[16][128];
    __shared__ float Bs[16][128];
    const int p0 = blockIdx.x * 128;
    const int c0 = blockIdx.y * 128;
    const int sb = blockIdx.z;
    const float* aft = &g_after[(size_t)sb * HW * REPC];

    const int t = threadIdx.x;
    const int tx = t & 15, ty = t >> 4;
    float acc[8][8];
    #pragma unroll
    for (int i = 0; i < 8; i++)
        #pragma unroll
        for (int j = 0; j < 8; j++) acc[i][j] = 0.f;

    for (int k0 = 0; k0 < REPC; k0 += 16) {
        int r = t >> 2, kk4 = (t & 3) * 4;
        #pragma unroll
        for (int rr = 0; rr < 128; rr += 64) {
            float4 v = *(const float4*)&up_w[(size_t)(c0 + r + rr) * REPC + k0 + kk4];
            As[kk4 + 0][r + rr] = v.x; As[kk4 + 1][r + rr] = v.y;
            As[kk4 + 2][r + rr] = v.z; As[kk4 + 3][r + rr] = v.w;
        }
        #pragma unroll
        for (int pp = 0; pp < 128; pp += 64) {
            float4 v = *(const float4*)&aft[(size_t)(p0 + r + pp) * REPC + k0 + kk4];
            Bs[kk4 + 0][r + pp] = v.x; Bs[kk4 + 1][r + pp] = v.y;
            Bs[kk4 + 2][r + pp] = v.z; Bs[kk4 + 3][r + pp] = v.w;
        }
        __syncthreads();
        #pragma unroll
        for (int kk = 0; kk < 16; kk++) {
            float4 a0 = *(const float4*)&As[kk][ty * 8];
            float4 a1 = *(const float4*)&As[kk][ty * 8 + 4];
            float4 b0 = *(const float4*)&Bs[kk][tx * 8];
            float4 b1 = *(const float4*)&Bs[kk][tx * 8 + 4];
            float a[8] = {a0.x, a0.y, a0.z, a0.w, a1.x, a1.y, a1.z, a1.w};
            float v[8] = {b0.x, b0.y, b0.z, b0.w, b1.x, b1.y, b1.z, b1.w};
            #pragma unroll
            for (int i = 0; i < 8; i++)
                #pragma unroll
                for (int j = 0; j < 8; j++)
                    acc[i][j] = fmaf(a[i], v[j], acc[i][j]);
        }
        __syncthreads();
    }
    #pragma unroll
    for (int i = 0; i < 8; i++) {
        int c = c0 + ty * 8 + i;
        float bi = up_b[c];
        float* o = &g_y[((size_t)sb * CH + c) * HW + p0 + tx * 8];
        *(float4*)&o[0] = make_float4(acc[i][0] + bi, acc[i][1] + bi,
                                      acc[i][2] + bi, acc[i][3] + bi);
        *(float4*)&o[4] = make_float4(acc[i][4] + bi, acc[i][5] + bi,
                                      acc[i][6] + bi, acc[i][7] + bi);
    }
}

// =========================================================================
// Kernel D: per-(side,channel) BN stats (deterministic tree reduce).
// =========================================================================
__global__ __launch_bounds__(256) void stats_kernel()
{
    const int c = blockIdx.x, side = blockIdx.y;
    const int t = threadIdx.x;
    float s = 0.f, s2 = 0.f;
    for (int b = 0; b < BATCH; b++) {
        const float* y = &g_y[(((size_t)side * BATCH + b) * CH + c) * HW];
        for (int p = t * 4; p < HW; p += 1024) {
            float4 v = *(const float4*)&y[p];
            s  += v.x + v.y + v.z + v.w;
            s2 += v.x * v.x + v.y * v.y + v.z * v.z + v.w * v.w;
        }
    }
    #pragma unroll
    for (int off = 16; off >= 1; off >>= 1) {
        s  += __shfl_xor_sync(0xffffffffu, s, off);
        s2 += __shfl_xor_sync(0xffffffffu, s2, off);
    }
    __shared__ float aw[8], aw2[8];
    if ((t & 31) == 0) { aw[t >> 5] = s; aw2[t >> 5] = s2; }
    __syncthreads();
    if (t == 0) {
        float S = 0.f, S2 = 0.f;
        #pragma unroll
        for (int w = 0; w < 8; w++) { S += aw[w]; S2 += aw2[w]; }
        g_stats[(side * CH + c) * 2 + 0] = S;
        g_stats[(side * CH + c) * 2 + 1] = S2;
    }
}

// =========================================================================
// Kernel E: BN apply + residual, write l_n / r_n.
// =========================================================================
__global__ __launch_bounds__(256) void bn_kernel(
    const float* __restrict__ left, const float* __restrict__ right,
    const float* __restrict__ gamma, const float* __restrict__ beta,
    float* __restrict__ d_out)
{
    const int side = blockIdx.y;
    const size_t idx = ((size_t)blockIdx.x * 256 + threadIdx.x) * 4;
    const int c = (int)((idx / HW) & (CH - 1));
    const float* xq = side ? right : left;

    float sum = g_stats[(side * CH + c) * 2 + 0];
    float sq  = g_stats[(side * CH + c) * 2 + 1];
    const float invN = 1.0f / (float)BHW;
    float mean = sum * invN;
    float var  = sq * invN - mean * mean;
    float sc   = rsqrtf(var + 1e-5f) * gamma[c];
    float bt   = beta[c];

    float4 y = *(const float4*)&g_y[(size_t)side * BCHW + idx];
    float4 x = *(const float4*)&xq[idx];
    float4 o;
    o.x = x.x + (y.x - mean) * sc + bt;
    o.y = x.y + (y.y - mean) * sc + bt;
    o.z = x.z + (y.z - mean) * sc + bt;
    o.w = x.w + (y.w - mean) * sc + bt;
    *(float4*)&d_out[(size_t)side * BCHW + idx] = o;
}

// =========================================================================
extern "C" void kernel_launch(void* const* d_in, const int* in_sizes, int n_in,
                              void* d_out, int out_size)
{
    const float* left    = (const float*)d_in[0];
    const float* right   = (const float*)d_in[1];
    const float* pre_l   = (const float*)d_in[2];
    const float* pre_r   = (const float*)d_in[3];
    const float* query_l = (const float*)d_in[4];
    const float* key_l   = (const float*)d_in[5];
    const float* query_r = (const float*)d_in[6];
    const float* key_r   = (const float*)d_in[7];
    const float* theta_w = (const float*)d_in[8];
    const float* theta_b = (const float*)d_in[9];
    const float* phi_w   = (const float*)d_in[10];
    const float* phi_b   = (const float*)d_in[11];
    const float* g_w     = (const float*)d_in[12];
    const float* g_b     = (const float*)d_in[13];
    const float* up_w    = (const float*)d_in[14];
    const float* up_b    = (const float*)d_in[15];
    const float* bn_g    = (const float*)d_in[16];
    const float* bn_b    = (const float*)d_in[17];
    float* out = (float*)d_out;

    cudaFuncSetAttribute(attn_kernel,
                         cudaFuncAttributeMaxDynamicSharedMemorySize, ATTN_SMEM);

    proj_kernel<<<dim3(32, BATCH, 6), 256>>>(
        left, right, pre_l, pre_r, query_l, key_l, query_r, key_r,
        theta_w, theta_b, phi_w, phi_b, g_w, g_b);

    attn_kernel<<<dim3(HW / 64, BATCH, NSIDE), 256, ATTN_SMEM>>>(out);

    up_kernel<<<dim3(32, 2, NSIDE * BATCH), 256>>>(up_w, up_b);

    stats_kernel<<<dim3(CH, NSIDE), 256>>>();

    bn_kernel<<<dim3(BCHW / 1024, NSIDE), 256>>>(left, right, bn_g, bn_b, out);
}

// round 4
// speedup vs baseline: 2.2744x; 2.2744x over previous
#include <cuda_runtime.h>
#include <cuda_bf16.h>
#include <math.h>

// Problem constants
#define BATCH 4
#define CH    256
#define REPC  128
#define HH    32
#define WWI   128
#define HW    4096              // H*W
#define NSIDE 2
#define BCHW  (BATCH*CH*HW)     // 4194304
#define BHW   (BATCH*HW)        // 16384

// -------- scratch (static device arrays; no runtime allocation) ----------
// bf16 hi/lo planes produced by proj_kernel, consumed by attn_kernel
__device__ __nv_bfloat16 g_th_h[NSIDE*BATCH*HW*REPC];  // theta [sb][q][d]
__device__ __nv_bfloat16 g_th_l[NSIDE*BATCH*HW*REPC];
__device__ __nv_bfloat16 g_k_h [NSIDE*BATCH*HW*REPC];  // phi   [sb][k][d]
__device__ __nv_bfloat16 g_k_l [NSIDE*BATCH*HW*REPC];
__device__ __nv_bfloat16 g_v_h [NSIDE*BATCH*REPC*HW];  // g     [sb][r][k]
__device__ __nv_bfloat16 g_v_l [NSIDE*BATCH*REPC*HW];
__device__ float g_after[NSIDE*BATCH*HW*REPC];   // [sb][p][r]
__device__ float g_y    [NSIDE*BATCH*CH*HW];     // [sb][c][p]
__device__ float g_stats[NSIDE*CH*2];            // [s][c][{sum,sumsq}]

__device__ __forceinline__ void cp_async16(void* smem_dst, const void* gsrc) {
    unsigned s = (unsigned)__cvta_generic_to_shared(smem_dst);
    asm volatile("cp.async.cg.shared.global [%0], [%1], 16;\n" :: "r"(s), "l"(gsrc));
}
#define CP_COMMIT() asm volatile("cp.async.commit_group;\n" ::: "memory")
#define CP_WAIT0()  asm volatile("cp.async.wait_group 0;\n" ::: "memory")

// bf16x2 pack helpers: low half-word = first argument = lower column index
__device__ __forceinline__ unsigned pack_hi(float a, float b, float& ra, float& rb) {
    __nv_bfloat162 h = __floats2bfloat162_rn(a, b);
    ra = a - __bfloat162float(h.x);
    rb = b - __bfloat162float(h.y);
    return *(unsigned*)&h;
}
__device__ __forceinline__ unsigned pack_pair(float a, float b) {
    __nv_bfloat162 h = __floats2bfloat162_rn(a, b);
    return *(unsigned*)&h;
}

__device__ __forceinline__ void mma16816(float c[4],
    unsigned a0, unsigned a1, unsigned a2, unsigned a3,
    unsigned b0, unsigned b1)
{
    asm volatile(
        "mma.sync.aligned.m16n8k16.row.col.f32.bf16.bf16.f32 "
        "{%0,%1,%2,%3}, {%4,%5,%6,%7}, {%8,%9}, {%0,%1,%2,%3};\n"
        : "+f"(c[0]), "+f"(c[1]), "+f"(c[2]), "+f"(c[3])
        : "r"(a0), "r"(a1), "r"(a2), "r"(a3), "r"(b0), "r"(b1));
}

// =========================================================================
// Kernel A: projection GEMMs.  grid (32, B, 6): z = side*3 + type
//   type 0: theta -> g_th_h/l [q][d]  (+ pre channel + query add)
//   type 1: phi   -> g_k_h/l  [k][d]  (+ key add)
//   type 2: g     -> g_v_h/l  [r][k]
// =========================================================================
__global__ __launch_bounds__(256) void proj_kernel(
    const float* __restrict__ left, const float* __restrict__ right,
    const float* __restrict__ pre_l, const float* __restrict__ pre_r,
    const float* __restrict__ query_l, const float* __restrict__ key_l,
    const float* __restrict__ query_r, const float* __restrict__ key_r,
    const float* __restrict__ theta_w, const float* __restrict__ theta_b,
    const float* __restrict__ phi_w, const float* __restrict__ phi_b,
    const float* __restrict__ gw, const float* __restrict__ gb)
{
    __shared__ float As[16][128];
    __shared__ float Bs[16][128];

    const int n0   = blockIdx.x * 128;
    const int b    = blockIdx.y;
    const int z    = blockIdx.z;
    const int side = z / 3;
    const int type = z - side * 3;

    const float* xq  = side ? right : left;
    const float* xkv = side ? left  : right;
    const float* X   = (type == 0) ? xq : xkv;
    const float* Wm  = (type == 0) ? theta_w : (type == 1 ? phi_w : gw);
    const float* bias= (type == 0) ? theta_b : (type == 1 ? phi_b : gb);
    const int    ldw = (type == 0) ? (CH + 1) : CH;
    X += (size_t)b * CH * HW;

    const int t  = threadIdx.x;
    const int tx = t & 15, ty = t >> 4;

    float acc[8][8];
    #pragma unroll
    for (int i = 0; i < 8; i++)
        #pragma unroll
        for (int j = 0; j < 8; j++) acc[i][j] = 0.f;

    for (int k0 = 0; k0 < CH; k0 += 16) {
        if (type == 0) {
            int r = t >> 1, kk8 = (t & 1) * 8;
            #pragma unroll
            for (int u = 0; u < 8; u++)
                As[kk8 + u][r] = Wm[(size_t)r * ldw + k0 + kk8 + u];
        } else {
            int r = t >> 2, kk4 = (t & 3) * 4;
            #pragma unroll
            for (int rr = 0; rr < 128; rr += 64) {
                float4 v = *(const float4*)&Wm[(size_t)(r + rr) * CH + k0 + kk4];
                As[kk4 + 0][r + rr] = v.x; As[kk4 + 1][r + rr] = v.y;
                As[kk4 + 2][r + rr] = v.z; As[kk4 + 3][r + rr] = v.w;
            }
        }
        {
            int kk = t >> 5, p4 = (t & 31) * 4;
            #pragma unroll
            for (int kr = 0; kr < 16; kr += 8)
                *(float4*)&Bs[kk + kr][p4] =
                    *(const float4*)&X[(size_t)(k0 + kk + kr) * HW + n0 + p4];
        }
        __syncthreads();
        #pragma unroll
        for (int kk = 0; kk < 16; kk++) {
            float4 a0 = *(const float4*)&As[kk][ty * 8];
            float4 a1 = *(const float4*)&As[kk][ty * 8 + 4];
            float4 b0 = *(const float4*)&Bs[kk][tx * 8];
            float4 b1 = *(const float4*)&Bs[kk][tx * 8 + 4];
            float a[8] = {a0.x, a0.y, a0.z, a0.w, a1.x, a1.y, a1.z, a1.w};
            float v[8] = {b0.x, b0.y, b0.z, b0.w, b1.x, b1.y, b1.z, b1.w};
            #pragma unroll
            for (int i = 0; i < 8; i++)
                #pragma unroll
                for (int j = 0; j < 8; j++)
                    acc[i][j] = fmaf(a[i], v[j], acc[i][j]);
        }
        __syncthreads();
    }

    const int sb = side * BATCH + b;
    if (type == 0) {
        const float* pre = side ? pre_r : pre_l;
        const float* qry = side ? query_r : query_l;
        float wp[8], pd[8];
        #pragma unroll
        for (int i = 0; i < 8; i++) wp[i] = Wm[(size_t)(ty * 8 + i) * ldw + CH];
        #pragma unroll
        for (int j = 0; j < 8; j++)
            pd[j] = pre[(size_t)b * HW + n0 + tx * 8 + j] * (1.0f / WWI);
        #pragma unroll
        for (int i = 0; i < 8; i++) {
            int r = ty * 8 + i;
            float bi = bias[r];
            #pragma unroll
            for (int j = 0; j < 8; j++) {
                int p = n0 + tx * 8 + j;
                acc[i][j] += wp[i] * pd[j] + bi +
                             qry[((size_t)b * REPC + r) * HW + p];
            }
        }
        #pragma unroll
        for (int j = 0; j < 8; j++) {
            int p = n0 + tx * 8 + j;
            size_t off = ((size_t)sb * HW + p) * REPC + ty * 8;
            unsigned h[4], l[4];
            #pragma unroll
            for (int u = 0; u < 4; u++) {
                float r0, r1;
                h[u] = pack_hi(acc[2*u][j], acc[2*u+1][j], r0, r1);
                l[u] = pack_pair(r0, r1);
            }
            *(uint4*)&g_th_h[off] = make_uint4(h[0], h[1], h[2], h[3]);
            *(uint4*)&g_th_l[off] = make_uint4(l[0], l[1], l[2], l[3]);
        }
    } else if (type == 1) {
        const float* keyf = side ? key_l : key_r;
        #pragma unroll
        for (int i = 0; i < 8; i++) {
            int r = ty * 8 + i;
            float bi = bias[r];
            #pragma unroll
            for (int j = 0; j < 8; j++)
                acc[i][j] += bi + keyf[((size_t)b * REPC + r) * HW + n0 + tx * 8 + j];
        }
        #pragma unroll
        for (int j = 0; j < 8; j++) {
            int p = n0 + tx * 8 + j;
            size_t off = ((size_t)sb * HW + p) * REPC + ty * 8;
            unsigned h[4], l[4];
            #pragma unroll
            for (int u = 0; u < 4; u++) {
                float r0, r1;
                h[u] = pack_hi(acc[2*u][j], acc[2*u+1][j], r0, r1);
                l[u] = pack_pair(r0, r1);
            }
            *(uint4*)&g_k_h[off] = make_uint4(h[0], h[1], h[2], h[3]);
            *(uint4*)&g_k_l[off] = make_uint4(l[0], l[1], l[2], l[3]);
        }
    } else {
        #pragma unroll
        for (int i = 0; i < 8; i++) {
            float bi = bias[ty * 8 + i];
            #pragma unroll
            for (int j = 0; j < 8; j++) acc[i][j] += bi;
        }
        #pragma unroll
        for (int i = 0; i < 8; i++) {
            int r = ty * 8 + i;
            size_t off = ((size_t)sb * REPC + r) * HW + n0 + tx * 8;
            unsigned h[4], l[4];
            #pragma unroll
            for (int u = 0; u < 4; u++) {
                float r0, r1;
                h[u] = pack_hi(acc[i][2*u], acc[i][2*u+1], r0, r1);
                l[u] = pack_pair(r0, r1);
            }
            *(uint4*)&g_v_h[off] = make_uint4(h[0], h[1], h[2], h[3]);
            *(uint4*)&g_v_l[off] = make_uint4(l[0], l[1], l[2], l[3]);
        }
    }
}

// =========================================================================
// Kernel B: flash-attention + soft-argmax on bf16 tensor cores (hi/lo split).
// grid (32, B, 2); 256 thr = 8 warps x 16 q-rows. Q tile 128, K tile 64.
// smem (bf16, padded rows): Qs 128x136 (hi,lo) + Ks 2buf x 64x136 (hi,lo)
//                           + Vt 2buf x 128x72 (hi,lo) = 212992 B
// =========================================================================
#define QROWPAD 136
#define VROWPAD 72
#define QS_EL   (128*QROWPAD)
#define KS_EL   (64*QROWPAD)
#define VS_EL   (128*VROWPAD)
#define ATTN_SMEM ((2*QS_EL + 4*KS_EL + 4*VS_EL) * 2)

__global__ __launch_bounds__(256) void attn_kernel(float* __restrict__ d_out)
{
    extern __shared__ __nv_bfloat16 smb[];
    __nv_bfloat16* QsH = smb;
    __nv_bfloat16* QsL = QsH + QS_EL;
    __nv_bfloat16* KsH = QsL + QS_EL;          // 2 bufs
    __nv_bfloat16* KsL = KsH + 2*KS_EL;
    __nv_bfloat16* VtH = KsL + 2*KS_EL;        // 2 bufs
    __nv_bfloat16* VtL = VtH + 2*VS_EL;

    const int q0   = blockIdx.x * 128;
    const int b    = blockIdx.y;
    const int side = blockIdx.z;
    const int sb   = side * BATCH + b;
    const int t    = threadIdx.x;
    const int wid  = t >> 5;
    const int lane = t & 31;
    const int g    = lane >> 2;      // 0..7 row group
    const int qr   = lane & 3;       // quad rank (col group)
    const int q0w  = wid * 16;       // warp's local q base

    const __nv_bfloat16* thH = g_th_h + ((size_t)sb * HW) * REPC;
    const __nv_bfloat16* thL = g_th_l + ((size_t)sb * HW) * REPC;
    const __nv_bfloat16* khG = g_k_h  + ((size_t)sb * HW) * REPC;
    const __nv_bfloat16* klG = g_k_l  + ((size_t)sb * HW) * REPC;
    const __nv_bfloat16* vhG = g_v_h  + ((size_t)sb * REPC) * HW;
    const __nv_bfloat16* vlG = g_v_l  + ((size_t)sb * REPC) * HW;

    // ---- prefetch K/V tile 0 + Q tile ----
    {
        int k = t >> 2;
        #pragma unroll
        for (int u = 0; u < 4; u++) {
            int ch = (t & 3) * 4 + u;
            cp_async16(&KsH[k * QROWPAD + ch * 8], &khG[(size_t)k * REPC + ch * 8]);
            cp_async16(&KsL[k * QROWPAD + ch * 8], &klG[(size_t)k * REPC + ch * 8]);
        }
        int r = t >> 1;
        #pragma unroll
        for (int u = 0; u < 4; u++) {
            int ch = (t & 1) * 4 + u;
            cp_async16(&VtH[r * VROWPAD + ch * 8], &vhG[(size_t)r * HW + ch * 8]);
            cp_async16(&VtL[r * VROWPAD + ch * 8], &vlG[(size_t)r * HW + ch * 8]);
        }
        int q = t >> 1;
        #pragma unroll
        for (int u = 0; u < 8; u++) {
            int ch = (t & 1) * 8 + u;
            cp_async16(&QsH[q * QROWPAD + ch * 8],
                       &thH[((size_t)(q0 + q)) * REPC + ch * 8]);
            cp_async16(&QsL[q * QROWPAD + ch * 8],
                       &thL[((size_t)(q0 + q)) * REPC + ch * 8]);
        }
        CP_COMMIT();
    }

    float O[16][4];
    #pragma unroll
    for (int rt = 0; rt < 16; rt++)
        #pragma unroll
        for (int u = 0; u < 4; u++) O[rt][u] = 0.f;
    float m0 = -1e30f, m1 = -1e30f, l0 = 0.f, l1 = 0.f, ca0 = 0.f, ca1 = 0.f;

    CP_WAIT0();
    __syncthreads();

    #pragma unroll 1
    for (int kt = 0; kt < 64; kt++) {
        const int cur = kt & 1;
        const __nv_bfloat16* Kh = KsH + cur * KS_EL;
        const __nv_bfloat16* Kl = KsL + cur * KS_EL;
        const __nv_bfloat16* Vh = VtH + cur * VS_EL;
        const __nv_bfloat16* Vl = VtL + cur * VS_EL;

        if (kt < 63) {
            const int k0n = (kt + 1) * 64;
            __nv_bfloat16* Kh2 = KsH + (1 - cur) * KS_EL;
            __nv_bfloat16* Kl2 = KsL + (1 - cur) * KS_EL;
            __nv_bfloat16* Vh2 = VtH + (1 - cur) * VS_EL;
            __nv_bfloat16* Vl2 = VtL + (1 - cur) * VS_EL;
            int k = t >> 2;
            #pragma unroll
            for (int u = 0; u < 4; u++) {
                int ch = (t & 3) * 4 + u;
                cp_async16(&Kh2[k * QROWPAD + ch * 8],
                           &khG[(size_t)(k0n + k) * REPC + ch * 8]);
                cp_async16(&Kl2[k * QROWPAD + ch * 8],
                           &klG[(size_t)(k0n + k) * REPC + ch * 8]);
            }
            int r = t >> 1;
            #pragma unroll
            for (int u = 0; u < 4; u++) {
                int ch = (t & 1) * 4 + u;
                cp_async16(&Vh2[r * VROWPAD + ch * 8],
                           &vhG[(size_t)r * HW + k0n + ch * 8]);
                cp_async16(&Vl2[r * VROWPAD + ch * 8],
                           &vlG[(size_t)r * HW + k0n + ch * 8]);
            }
            CP_COMMIT();
        }

        // ---- S = Q K^T via mma (hi/lo 3-term split), C[8 ntiles][4] ----
        float C[8][4];
        #pragma unroll
        for (int nt = 0; nt < 8; nt++)
            #pragma unroll
            for (int u = 0; u < 4; u++) C[nt][u] = 0.f;

        #pragma unroll 1
        for (int dc = 0; dc < 8; dc++) {
            const int dof = dc * 16 + 2 * qr;
            const __nv_bfloat16* qrow0 = QsH + (q0w + g) * QROWPAD;
            const __nv_bfloat16* qrow8 = QsH + (q0w + g + 8) * QROWPAD;
            unsigned a0h = *(const unsigned*)&qrow0[dof];
            unsigned a1h = *(const unsigned*)&qrow8[dof];
            unsigned a2h = *(const unsigned*)&qrow0[dof + 8];
            unsigned a3h = *(const unsigned*)&qrow8[dof + 8];
            const __nv_bfloat16* qlow0 = QsL + (q0w + g) * QROWPAD;
            const __nv_bfloat16* qlow8 = QsL + (q0w + g + 8) * QROWPAD;
            unsigned a0l = *(const unsigned*)&qlow0[dof];
            unsigned a1l = *(const unsigned*)&qlow8[dof];
            unsigned a2l = *(const unsigned*)&qlow0[dof + 8];
            unsigned a3l = *(const unsigned*)&qlow8[dof + 8];
            #pragma unroll
            for (int nt = 0; nt < 8; nt++) {
                const __nv_bfloat16* krow = Kh + (nt * 8 + g) * QROWPAD;
                unsigned b0h = *(const unsigned*)&krow[dof];
                unsigned b1h = *(const unsigned*)&krow[dof + 8];
                const __nv_bfloat16* klow = Kl + (nt * 8 + g) * QROWPAD;
                unsigned b0l = *(const unsigned*)&klow[dof];
                unsigned b1l = *(const unsigned*)&klow[dof + 8];
                mma16816(C[nt], a0h, a1h, a2h, a3h, b0h, b1h);
                mma16816(C[nt], a0l, a1l, a2l, a3l, b0h, b1h);
                mma16816(C[nt], a0h, a1h, a2h, a3h, b0l, b1l);
            }
        }

        // ---- online softmax (rows g and g+8; cols in quad lanes) ----
        const int k0 = kt * 64;
        float mloc0 = -1e30f, mloc1 = -1e30f;
        #pragma unroll
        for (int nt = 0; nt < 8; nt++) {
            mloc0 = fmaxf(mloc0, fmaxf(C[nt][0], C[nt][1]));
            mloc1 = fmaxf(mloc1, fmaxf(C[nt][2], C[nt][3]));
        }
        #pragma unroll
        for (int off = 1; off <= 2; off <<= 1) {
            mloc0 = fmaxf(mloc0, __shfl_xor_sync(0xffffffffu, mloc0, off));
            mloc1 = fmaxf(mloc1, __shfl_xor_sync(0xffffffffu, mloc1, off));
        }
        float mn0 = fmaxf(m0, mloc0), mn1 = fmaxf(m1, mloc1);
        float co0 = __expf(m0 - mn0), co1 = __expf(m1 - mn1);
        float ps0 = 0.f, ps1 = 0.f, cs0 = 0.f, cs1 = 0.f;
        #pragma unroll
        for (int nt = 0; nt < 8; nt++) {
            float col = (float)((k0 + nt * 8 + 2 * qr) & (WWI - 1));
            float p00 = __expf(C[nt][0] - mn0);
            float p01 = __expf(C[nt][1] - mn0);
            float p10 = __expf(C[nt][2] - mn1);
            float p11 = __expf(C[nt][3] - mn1);
            C[nt][0] = p00; C[nt][1] = p01; C[nt][2] = p10; C[nt][3] = p11;
            ps0 += p00 + p01;            ps1 += p10 + p11;
            cs0 += p00 * col + p01 * (col + 1.f);
            cs1 += p10 * col + p11 * (col + 1.f);
        }
        #pragma unroll
        for (int off = 1; off <= 2; off <<= 1) {
            ps0 += __shfl_xor_sync(0xffffffffu, ps0, off);
            ps1 += __shfl_xor_sync(0xffffffffu, ps1, off);
            cs0 += __shfl_xor_sync(0xffffffffu, cs0, off);
            cs1 += __shfl_xor_sync(0xffffffffu, cs1, off);
        }
        l0 = l0 * co0 + ps0;  ca0 = ca0 * co0 + cs0;  m0 = mn0;
        l1 = l1 * co1 + ps1;  ca1 = ca1 * co1 + cs1;  m1 = mn1;

        // rescale O
        #pragma unroll
        for (int rt = 0; rt < 16; rt++) {
            O[rt][0] *= co0; O[rt][1] *= co0;
            O[rt][2] *= co1; O[rt][3] *= co1;
        }

        // ---- P -> bf16 hi/lo A fragments (in registers) ----
        unsigned PH[8][2], PL[8][2];
        #pragma unroll
        for (int nt = 0; nt < 8; nt++) {
            float r0, r1;
            PH[nt][0] = pack_hi(C[nt][0], C[nt][1], r0, r1);
            PL[nt][0] = pack_pair(r0, r1);
            PH[nt][1] = pack_hi(C[nt][2], C[nt][3], r0, r1);
            PL[nt][1] = pack_pair(r0, r1);
        }

        // ---- O += P V (hi/lo 3-term split) ----
        #pragma unroll 1
        for (int kc = 0; kc < 4; kc++) {
            unsigned ah0 = PH[2*kc][0],   ah1 = PH[2*kc][1];
            unsigned ah2 = PH[2*kc+1][0], ah3 = PH[2*kc+1][1];
            unsigned al0 = PL[2*kc][0],   al1 = PL[2*kc][1];
            unsigned al2 = PL[2*kc+1][0], al3 = PL[2*kc+1][1];
            const int ko = kc * 16 + 2 * qr;
            #pragma unroll
            for (int rt = 0; rt < 16; rt++) {
                const __nv_bfloat16* vr = Vh + (rt * 8 + g) * VROWPAD;
                unsigned b0h = *(const unsigned*)&vr[ko];
                unsigned b1h = *(const unsigned*)&vr[ko + 8];
                const __nv_bfloat16* vl = Vl + (rt * 8 + g) * VROWPAD;
                unsigned b0l = *(const unsigned*)&vl[ko];
                unsigned b1l = *(const unsigned*)&vl[ko + 8];
                mma16816(O[rt], ah0, ah1, ah2, ah3, b0h, b1h);
                mma16816(O[rt], al0, al1, al2, al3, b0h, b1h);
                mma16816(O[rt], ah0, ah1, ah2, ah3, b0l, b1l);
            }
        }

        CP_WAIT0();
        __syncthreads();
    }

    // ---- finalize ----
    const int qg0 = q0 + q0w + g;
    const int qg1 = qg0 + 8;
    float inv0 = 1.0f / l0, inv1 = 1.0f / l1;
    float* aft = g_after + ((size_t)sb * HW) * REPC;
    #pragma unroll
    for (int rt = 0; rt < 16; rt++) {
        int rc = rt * 8 + 2 * qr;
        float2 v0 = make_float2(O[rt][0] * inv0, O[rt][1] * inv0);
        float2 v1 = make_float2(O[rt][2] * inv1, O[rt][3] * inv1);
        *(float2*)&aft[(size_t)qg0 * REPC + rc] = v0;
        *(float2*)&aft[(size_t)qg1 * REPC + rc] = v1;
    }
    if (qr == 0) {
        size_t ib = 2 * (size_t)BCHW + (size_t)side * BHW + (size_t)b * HW;
        d_out[ib + qg0] = (float)(qg0 & (WWI - 1)) - ca0 * inv0;
        d_out[ib + qg1] = (float)(qg1 & (WWI - 1)) - ca1 * inv1;
    }
}

// =========================================================================
// Kernel C: up-projection y = up_w @ after^T + up_b.
// =========================================================================
__global__ __launch_bounds__(256) void up_kernel(
    const float* __restrict__ up_w, const float* __restrict__ up_b)
{
    __shared__ float As[16][128];
    __shared__ float Bs[16][128];
    const int p0 = blockIdx.x * 128;
    const int c0 = blockIdx.y * 128;
    const int sb = blockIdx.z;
    const float* aft = &g_after[(size_t)sb * HW * REPC];

    const int t = threadIdx.x;
    const int tx = t & 15, ty = t >> 4;
    float acc[8][8];
    #pragma unroll
    for (int i = 0; i < 8; i++)
        #pragma unroll
        for (int j = 0; j < 8; j++) acc[i][j] = 0.f;

    for (int k0 = 0; k0 < REPC; k0 += 16) {
        int r = t >> 2, kk4 = (t & 3) * 4;
        #pragma unroll
        for (int rr = 0; rr < 128; rr += 64) {
            float4 v = *(const float4*)&up_w[(size_t)(c0 + r + rr) * REPC + k0 + kk4];
            As[kk4 + 0][r + rr] = v.x; As[kk4 + 1][r + rr] = v.y;
            As[kk4 + 2][r + rr] = v.z; As[kk4 + 3][r + rr] = v.w;
        }
        #pragma unroll
        for (int pp = 0; pp < 128; pp += 64) {
            float4 v = *(const float4*)&aft[(size_t)(p0 + r + pp) * REPC + k0 + kk4];
            Bs[kk4 + 0][r + pp] = v.x; Bs[kk4 + 1][r + pp] = v.y;
            Bs[kk4 + 2][r + pp] = v.z; Bs[kk4 + 3][r + pp] = v.w;
        }
        __syncthreads();
        #pragma unroll
        for (int kk = 0; kk < 16; kk++) {
            float4 a0 = *(const float4*)&As[kk][ty * 8];
            float4 a1 = *(const float4*)&As[kk][ty * 8 + 4];
            float4 b0 = *(const float4*)&Bs[kk][tx * 8];
            float4 b1 = *(const float4*)&Bs[kk][tx * 8 + 4];
            float a[8] = {a0.x, a0.y, a0.z, a0.w, a1.x, a1.y, a1.z, a1.w};
            float v[8] = {b0.x, b0.y, b0.z, b0.w, b1.x, b1.y, b1.z, b1.w};
            #pragma unroll
            for (int i = 0; i < 8; i++)
                #pragma unroll
                for (int j = 0; j < 8; j++)
                    acc[i][j] = fmaf(a[i], v[j], acc[i][j]);
        }
        __syncthreads();
    }
    #pragma unroll
    for (int i = 0; i < 8; i++) {
        int c = c0 + ty * 8 + i;
        float bi = up_b[c];
        float* o = &g_y[((size_t)sb * CH + c) * HW + p0 + tx * 8];
        *(float4*)&o[0] = make_float4(acc[i][0] + bi, acc[i][1] + bi,
                                      acc[i][2] + bi, acc[i][3] + bi);
        *(float4*)&o[4] = make_float4(acc[i][4] + bi, acc[i][5] + bi,
                                      acc[i][6] + bi, acc[i][7] + bi);
    }
}

// =========================================================================
// Kernel D: per-(side,channel) BN stats (deterministic tree reduce).
// =========================================================================
__global__ __launch_bounds__(256) void stats_kernel()
{
    const int c = blockIdx.x, side = blockIdx.y;
    const int t = threadIdx.x;
    float s = 0.f, s2 = 0.f;
    for (int b = 0; b < BATCH; b++) {
        const float* y = &g_y[(((size_t)side * BATCH + b) * CH + c) * HW];
        for (int p = t * 4; p < HW; p += 1024) {
            float4 v = *(const float4*)&y[p];
            s  += v.x + v.y + v.z + v.w;
            s2 += v.x * v.x + v.y * v.y + v.z * v.z + v.w * v.w;
        }
    }
    #pragma unroll
    for (int off = 16; off >= 1; off >>= 1) {
        s  += __shfl_xor_sync(0xffffffffu, s, off);
        s2 += __shfl_xor_sync(0xffffffffu, s2, off);
    }
    __shared__ float aw[8], aw2[8];
    if ((t & 31) == 0) { aw[t >> 5] = s; aw2[t >> 5] = s2; }
    __syncthreads();
    if (t == 0) {
        float S = 0.f, S2 = 0.f;
        #pragma unroll
        for (int w = 0; w < 8; w++) { S += aw[w]; S2 += aw2[w]; }
        g_stats[(side * CH + c) * 2 + 0] = S;
        g_stats[(side * CH + c) * 2 + 1] = S2;
    }
}

// =========================================================================
// Kernel E: BN apply + residual, write l_n / r_n.
// =========================================================================
__global__ __launch_bounds__(256) void bn_kernel(
    const float* __restrict__ left, const float* __restrict__ right,
    const float* __restrict__ gamma, const float* __restrict__ beta,
    float* __restrict__ d_out)
{
    const int side = blockIdx.y;
    const size_t idx = ((size_t)blockIdx.x * 256 + threadIdx.x) * 4;
    const int c = (int)((idx / HW) & (CH - 1));
    const float* xq = side ? right : left;

    float sum = g_stats[(side * CH + c) * 2 + 0];
    float sq  = g_stats[(side * CH + c) * 2 + 1];
    const float invN = 1.0f / (float)BHW;
    float mean = sum * invN;
    float var  = sq * invN - mean * mean;
    float sc   = rsqrtf(var + 1e-5f) * gamma[c];
    float bt   = beta[c];

    float4 y = *(const float4*)&g_y[(size_t)side * BCHW + idx];
    float4 x = *(const float4*)&xq[idx];
    float4 o;
    o.x = x.x + (y.x - mean) * sc + bt;
    o.y = x.y + (y.y - mean) * sc + bt;
    o.z = x.z + (y.z - mean) * sc + bt;
    o.w = x.w + (y.w - mean) * sc + bt;
    *(float4*)&d_out[(size_t)side * BCHW + idx] = o;
}

// =========================================================================
extern "C" void kernel_launch(void* const* d_in, const int* in_sizes, int n_in,
                              void* d_out, int out_size)
{
    const float* left    = (const float*)d_in[0];
    const float* right   = (const float*)d_in[1];
    const float* pre_l   = (const float*)d_in[2];
    const float* pre_r   = (const float*)d_in[3];
    const float* query_l = (const float*)d_in[4];
    const float* key_l   = (const float*)d_in[5];
    const float* query_r = (const float*)d_in[6];
    const float* key_r   = (const float*)d_in[7];
    const float* theta_w = (const float*)d_in[8];
    const float* theta_b = (const float*)d_in[9];
    const float* phi_w   = (const float*)d_in[10];
    const float* phi_b   = (const float*)d_in[11];
    const float* g_w     = (const float*)d_in[12];
    const float* g_b     = (const float*)d_in[13];
    const float* up_w    = (const float*)d_in[14];
    const float* up_b    = (const float*)d_in[15];
    const float* bn_g    = (const float*)d_in[16];
    const float* bn_b    = (const float*)d_in[17];
    float* out = (float*)d_out;

    cudaFuncSetAttribute(attn_kernel,
                         cudaFuncAttributeMaxDynamicSharedMemorySize, ATTN_SMEM);

    proj_kernel<<<dim3(32, BATCH, 6), 256>>>(
        left, right, pre_l, pre_r, query_l, key_l, query_r, key_r,
        theta_w, theta_b, phi_w, phi_b, g_w, g_b);

    attn_kernel<<<dim3(32, BATCH, NSIDE), 256, ATTN_SMEM>>>(out);

    up_kernel<<<dim3(32, 2, NSIDE * BATCH), 256>>>(up_w, up_b);

    stats_kernel<<<dim3(CH, NSIDE), 256>>>();

    bn_kernel<<<dim3(BCHW / 1024, NSIDE), 256>>>(left, right, bn_g, bn_b, out);
}